// round 1
// baseline (speedup 1.0000x reference)
#include <cuda_runtime.h>
#include <cstddef>

// Problem dims
#define CB 128     // batch
#define CL 64      // feature pixels
#define CT 20      // decode steps
#define CV 32000   // vocab
#define CE 512     // embed
#define CH 1024    // hidden
#define CA 512     // attn dim
#define CF 2048    // num_features
#define CEFH 3584  // E + F + H  (lstm_in layout: [emb | context | h])
#define G4 4096    // 4*H

// ---------------- device scratch (no allocations allowed) ----------------
__device__ float g_mean [CB * CF];
__device__ float g_c    [CB * CH];
__device__ float g_xenc [CB * CL * CA];
__device__ float g_xd   [CB * CA];
__device__ float g_lstm [CB * CEFH];           // [emb(512) | context(2048) | h(1024)]
__device__ float g_gates[CB * G4];
__device__ float g_wc   [CEFH * G4];           // [w_ih ; w_hh] stacked rows
__device__ float g_bc   [G4];                  // b_ih + b_hh

// ---------------- generic tiled SGEMM: C = A[M,K] @ B[K,N] (+bias) -------
// Row-major A (lda), row-major B (ldb), row-major C (ldc).
// All dims must be exact multiples of the tile sizes (guaranteed by caller).
template<int BM, int BN, int BK, int TM, int TN, int NT>
__global__ __launch_bounds__(NT)
void sgemm_kernel(const float* __restrict__ A, int lda,
                  const float* __restrict__ B, int ldb,
                  float* __restrict__ C, int ldc,
                  int K, const float* __restrict__ bias)
{
    __shared__ float As[BK][BM];
    __shared__ float Bs[BK][BN];
    const int tid = threadIdx.x;
    const size_t mbase = (size_t)blockIdx.y * BM;
    const size_t nbase = (size_t)blockIdx.x * BN;
    A += mbase * (size_t)lda;
    B += nbase;
    C += mbase * (size_t)ldc + nbase;
    if (bias) bias += nbase;

    const int tcol = (tid % (BN / TN)) * TN;
    const int trow = (tid / (BN / TN)) * TM;

    float acc[TM][TN];
#pragma unroll
    for (int i = 0; i < TM; i++)
#pragma unroll
        for (int j = 0; j < TN; j++) acc[i][j] = 0.f;

    constexpr int KV = BK / 4;           // float4s per A row chunk
    for (int k0 = 0; k0 < K; k0 += BK) {
        // load A tile (BM x BK), store transposed As[k][m]
#pragma unroll
        for (int it = 0; it < (BM * KV) / NT; it++) {
            int idx = tid + it * NT;
            int row = idx / KV;
            int cv  = (idx % KV) * 4;
            float4 v = *(const float4*)(A + (size_t)row * lda + k0 + cv);
            As[cv + 0][row] = v.x;
            As[cv + 1][row] = v.y;
            As[cv + 2][row] = v.z;
            As[cv + 3][row] = v.w;
        }
        // load B tile (BK x BN)
#pragma unroll
        for (int it = 0; it < (BK * BN / 4) / NT; it++) {
            int idx = tid + it * NT;
            int row = idx / (BN / 4);
            int cv  = (idx % (BN / 4)) * 4;
            *(float4*)(&Bs[row][cv]) = *(const float4*)(B + (size_t)(k0 + row) * ldb + cv);
        }
        __syncthreads();
#pragma unroll
        for (int k = 0; k < BK; k++) {
            float ra[TM], rb[TN];
#pragma unroll
            for (int i = 0; i < TM; i += 4)
                *(float4*)(ra + i) = *(const float4*)(&As[k][trow + i]);
#pragma unroll
            for (int j = 0; j < TN; j += 4)
                *(float4*)(rb + j) = *(const float4*)(&Bs[k][tcol + j]);
#pragma unroll
            for (int i = 0; i < TM; i++)
#pragma unroll
                for (int j = 0; j < TN; j++)
                    acc[i][j] = fmaf(ra[i], rb[j], acc[i][j]);
        }
        __syncthreads();
    }

#pragma unroll
    for (int i = 0; i < TM; i++) {
#pragma unroll
        for (int j = 0; j < TN; j += 4) {
            float4 v;
            v.x = acc[i][j + 0]; v.y = acc[i][j + 1];
            v.z = acc[i][j + 2]; v.w = acc[i][j + 3];
            if (bias) {
                v.x += bias[tcol + j + 0]; v.y += bias[tcol + j + 1];
                v.z += bias[tcol + j + 2]; v.w += bias[tcol + j + 3];
            }
            *(float4*)(C + (size_t)(trow + i) * ldc + tcol + j) = v;
        }
    }
}

// ---------------- pointwise / fused kernels ----------------

// mean over L: g_mean[b,f] = (1/L) * sum_l X[b,l,f]
__global__ void mean_kernel(const float* __restrict__ X, float* __restrict__ mean)
{
    int idx = blockIdx.x * blockDim.x + threadIdx.x;      // B*F
    int b = idx >> 11;            // /2048
    int f = idx & (CF - 1);
    const float* xb = X + (size_t)b * CL * CF + f;
    float s = 0.f;
#pragma unroll 8
    for (int l = 0; l < CL; l++) s += xb[(size_t)l * CF];
    mean[idx] = s * (1.0f / CL);
}

// build combined LSTM weight [3584,4096] = [w_ih ; w_hh]
__global__ void build_wcomb(const float* __restrict__ w_ih,
                            const float* __restrict__ w_hh,
                            float* __restrict__ wc)
{
    size_t idx = (size_t)blockIdx.x * blockDim.x + threadIdx.x;
    const size_t split = (size_t)(CE + CF) * G4;   // 2560*4096
    wc[idx] = (idx < split) ? w_ih[idx] : w_hh[idx - split];
}

__global__ void build_bcomb(const float* __restrict__ b_ih,
                            const float* __restrict__ b_hh,
                            float* __restrict__ bc)
{
    int i = blockIdx.x * blockDim.x + threadIdx.x;
    bc[i] = b_ih[i] + b_hh[i];
}

// gather embedding row for token y[b, t] into lstm_in[b, 0:E]
__global__ void emb_gather(const int* __restrict__ y,
                           const float* __restrict__ emb,
                           float* __restrict__ lstm, int t)
{
    int idx = blockIdx.x * blockDim.x + threadIdx.x;  // B*E
    int b = idx >> 9;             // /512
    int e = idx & (CE - 1);
    int tok = y[b * (CT + 1) + t];
    lstm[(size_t)b * CEFH + e] = emb[(size_t)tok * CE + e];
}

// fused attention: scores -> softmax -> alpha (to output) -> context (to lstm_in)
__global__ __launch_bounds__(256)
void attn_kernel(const float* __restrict__ X,
                 const float* __restrict__ xenc,
                 const float* __restrict__ xd,
                 const float* __restrict__ score_w,
                 const float* __restrict__ score_b,
                 float* __restrict__ alpha_out,     // may be null
                 float* __restrict__ lstm, int t)
{
    const int b = blockIdx.x;
    __shared__ float sxd[CA];
    __shared__ float ssw[CA];
    __shared__ float ssc[CL];
    __shared__ float salpha[CL];
    const int tid = threadIdx.x;
    const int warp = tid >> 5, lane = tid & 31;

    for (int i = tid; i < CA; i += 256) {
        sxd[i] = xd[b * CA + i];
        ssw[i] = score_w[i];
    }
    __syncthreads();

    // scores[l] = sum_a tanh(xenc[b,l,a] + xd[b,a]) * score_w[a]
    for (int l = warp; l < CL; l += 8) {
        const float* xe = xenc + ((size_t)b * CL + l) * CA;
        float acc = 0.f;
        for (int a = lane; a < CA; a += 32)
            acc += tanhf(xe[a] + sxd[a]) * ssw[a];
#pragma unroll
        for (int off = 16; off; off >>= 1)
            acc += __shfl_xor_sync(0xffffffffu, acc, off);
        if (lane == 0) ssc[l] = acc + score_b[0];
    }
    __syncthreads();

    // softmax over L=64 by warp 0
    if (warp == 0) {
        float v0 = ssc[lane], v1 = ssc[lane + 32];
        float m = fmaxf(v0, v1);
#pragma unroll
        for (int off = 16; off; off >>= 1)
            m = fmaxf(m, __shfl_xor_sync(0xffffffffu, m, off));
        float e0 = expf(v0 - m), e1 = expf(v1 - m);
        float s = e0 + e1;
#pragma unroll
        for (int off = 16; off; off >>= 1)
            s += __shfl_xor_sync(0xffffffffu, s, off);
        float inv = 1.0f / s;
        salpha[lane]      = e0 * inv;
        salpha[lane + 32] = e1 * inv;
    }
    __syncthreads();

    if (alpha_out && tid < CL)
        alpha_out[((size_t)b * CT + t) * CL + tid] = salpha[tid];

    // context[b,f] = sum_l alpha[l] * X[b,l,f]  -> lstm_in[b, E + f]
    const float* Xb = X + (size_t)b * CL * CF;
    for (int f = tid; f < CF; f += 256) {
        float acc = 0.f;
#pragma unroll 8
        for (int l = 0; l < CL; l++)
            acc += salpha[l] * Xb[(size_t)l * CF + f];
        lstm[(size_t)b * CEFH + CE + f] = acc;
    }
}

__device__ __forceinline__ float sigm(float x) { return 1.0f / (1.0f + expf(-x)); }

// LSTM pointwise: reads gates[B,4H], c; writes c and h2 into lstm_in[:, 2560:]
__global__ void lstm_cell(const float* __restrict__ gates,
                          float* __restrict__ c,
                          float* __restrict__ lstm)
{
    int idx = blockIdx.x * blockDim.x + threadIdx.x;  // B*H
    int b = idx >> 10;           // /1024
    int j = idx & (CH - 1);
    const float* g = gates + (size_t)b * G4;
    float gi = sigm(g[j]);
    float gf = sigm(g[j + CH]);
    float gg = tanhf(g[j + 2 * CH]);
    float go = sigm(g[j + 3 * CH]);
    float c2 = gf * c[idx] + gi * gg;
    c[idx] = c2;
    lstm[(size_t)b * CEFH + CE + CF + j] = go * tanhf(c2);
}

// ---------------- host-side launch helpers ----------------
static void gemm128(const float* A, int lda, const float* B, int ldb,
                    float* C, int ldc, int M, int N, int K, const float* bias)
{
    dim3 grid(N / 128, M / 128);
    sgemm_kernel<128, 128, 8, 8, 8, 256><<<grid, 256>>>(A, lda, B, ldb, C, ldc, K, bias);
}
static void gemm64(const float* A, int lda, const float* B, int ldb,
                   float* C, int ldc, int M, int N, int K, const float* bias)
{
    dim3 grid(N / 64, M / 64);
    sgemm_kernel<64, 64, 8, 8, 4, 128><<<grid, 128>>>(A, lda, B, ldb, C, ldc, K, bias);
}

extern "C" void kernel_launch(void* const* d_in, const int* in_sizes, int n_in,
                              void* d_out, int out_size)
{
    const float* X       = (const float*)d_in[0];
    const int*   y       = (const int*)  d_in[1];   // jax default x64-off -> int32
    const float* emb     = (const float*)d_in[2];
    const float* fc1_w   = (const float*)d_in[3];
    const float* fc1_b   = (const float*)d_in[4];
    const float* fc2_w   = (const float*)d_in[5];
    const float* fc2_b   = (const float*)d_in[6];
    const float* score_w = (const float*)d_in[7];
    const float* score_b = (const float*)d_in[8];
    const float* sm_w    = (const float*)d_in[9];
    const float* sm_b    = (const float*)d_in[10];
    const float* lm_w    = (const float*)d_in[11];
    // const float* sm_b2 unused
    const float* lm_b    = (const float*)d_in[12];
    const float* w_ih    = (const float*)d_in[13];
    const float* b_ih    = (const float*)d_in[14];
    const float* w_hh    = (const float*)d_in[15];
    const float* b_hh    = (const float*)d_in[16];
    const float* out_w   = (const float*)d_in[17];
    const float* out_b   = (const float*)d_in[18];

    float* out        = (float*)d_out;
    float* out_logits = out;
    const size_t logits_elems = (size_t)CB * CT * CV;
    const size_t total_elems  = logits_elems + (size_t)CB * CT * CL;
    float* out_alpha = ((size_t)out_size >= total_elems) ? (out + logits_elems) : nullptr;

    float *mean, *c, *xenc, *xd, *lstm, *gates, *wc, *bc;
    cudaGetSymbolAddress((void**)&mean,  g_mean);
    cudaGetSymbolAddress((void**)&c,     g_c);
    cudaGetSymbolAddress((void**)&xenc,  g_xenc);
    cudaGetSymbolAddress((void**)&xd,    g_xd);
    cudaGetSymbolAddress((void**)&lstm,  g_lstm);
    cudaGetSymbolAddress((void**)&gates, g_gates);
    cudaGetSymbolAddress((void**)&wc,    g_wc);
    cudaGetSymbolAddress((void**)&bc,    g_bc);

    // ---- prologue ----
    mean_kernel<<<(CB * CF) / 256, 256>>>(X, mean);
    // h0 -> lstm_in[:, 2560:] (h slot), c0 -> g_c
    gemm64(mean, CF, sm_w, CH, lstm + (CE + CF), CEFH, CB, CH, CF, sm_b);
    gemm64(mean, CF, lm_w, CH, c, CH, CB, CH, CF, lm_b);
    // x_enc = X @ fc2_w + fc2_b : [B*L, A]
    gemm128(X, CF, fc2_w, CA, xenc, CA, CB * CL, CA, CF, fc2_b);
    // combined LSTM weight & bias
    build_wcomb<<<(unsigned)(((size_t)CEFH * G4) / 256), 256>>>(w_ih, w_hh, wc);
    build_bcomb<<<G4 / 256, 256>>>(b_ih, b_hh, bc);

    // ---- decode loop ----
    for (int t = 0; t < CT; t++) {
        // xd = h @ fc1_w + fc1_b    (h lives inside lstm_in)
        gemm64(lstm + (CE + CF), CEFH, fc1_w, CA, xd, CA, CB, CA, CH, fc1_b);
        // embedding gather for this step
        emb_gather<<<(CB * CE) / 256, 256>>>(y, emb, lstm, t);
        // attention: alpha -> output, context -> lstm_in[:, 512:2560]
        attn_kernel<<<CB, 256>>>(X, xenc, xd, score_w, score_b, out_alpha, lstm, t);
        // gates = lstm_in[B,3584] @ wc[3584,4096] + (b_ih + b_hh)
        gemm64(lstm, CEFH, wc, G4, gates, G4, CB, G4, CEFH, bc);
        // LSTM pointwise: update c, write h2 into lstm_in h slot
        lstm_cell<<<(CB * CH) / 256, 256>>>(gates, c, lstm);
        // logits = h2 @ out_w + out_b -> outputs[:, t, :]
        gemm128(lstm + (CE + CF), CEFH, out_w, CV,
                out_logits + (size_t)t * CV, CT * CV, CB, CV, CH, out_b);
    }
}

// round 3
// speedup vs baseline: 3.1244x; 3.1244x over previous
#include <cuda_runtime.h>
#include <cuda_bf16.h>
#include <cstdint>
#include <cstddef>

// Problem dims
#define CB 128     // batch
#define CL 64      // feature pixels
#define CT 20      // decode steps
#define CV 32000   // vocab
#define CE 512     // embed
#define CH 1024    // hidden
#define CA 512     // attn dim
#define CF 2048    // num_features
#define CEFH 3584  // E + F + H  (lstm_in layout: [emb | context | h])
#define G4 4096    // 4*H

// ---------------- device scratch (no allocations allowed) ----------------
__device__ float g_mean [CB * CF];
__device__ float g_c    [CB * CH];
__device__ float g_xenc [CB * CL * CA];
__device__ float g_xd   [CB * CA];
__device__ float g_lstm [CB * CEFH];           // fp32 staging [emb|context|h0]
__device__ float g_gates[CB * G4];
__device__ float g_wc   [(size_t)CEFH * G4];   // [w_ih ; w_hh] stacked rows (fp32)
__device__ float g_bc   [G4];                  // b_ih + b_hh

// bf16 hi/lo split operands (16B aligned for cp.async / float4)
__device__ __align__(16) __nv_bfloat16 g_lstm_hi[CB * CEFH],  g_lstm_lo[CB * CEFH];
__device__ __align__(16) __nv_bfloat16 g_X_hi [(size_t)CB * CL * CF], g_X_lo [(size_t)CB * CL * CF];
__device__ __align__(16) __nv_bfloat16 g_owT_hi[(size_t)CV * CH],     g_owT_lo[(size_t)CV * CH];   // [V, H]
__device__ __align__(16) __nv_bfloat16 g_wcT_hi[(size_t)G4 * CEFH],   g_wcT_lo[(size_t)G4 * CEFH]; // [4H, 3584]
__device__ __align__(16) __nv_bfloat16 g_f2T_hi[(size_t)CA * CF],     g_f2T_lo[(size_t)CA * CF];   // [A, F]
__device__ __align__(16) __nv_bfloat16 g_f1T_hi[(size_t)CA * CH],     g_f1T_lo[(size_t)CA * CH];   // [A, H]

// ================= base-PTX tensor-core helpers (sm_80+, valid on sm_103) =================
__device__ __forceinline__ uint32_t smem_u32(const void* p) {
    uint32_t a;
    asm("{ .reg .u64 t; cvta.to.shared.u64 t, %1; cvt.u32.u64 %0, t; }" : "=r"(a) : "l"(p));
    return a;
}
__device__ __forceinline__ void cp16(uint32_t dst, const void* src) {
    asm volatile("cp.async.cg.shared.global [%0], [%1], 16;" :: "r"(dst), "l"(src));
}
__device__ __forceinline__ void cp_commit() {
    asm volatile("cp.async.commit_group;" ::: "memory");
}
template<int N>
__device__ __forceinline__ void cp_wait() {
    asm volatile("cp.async.wait_group %0;" :: "n"(N) : "memory");
}
__device__ __forceinline__ void ldsm4(uint32_t* r, uint32_t addr) {
    asm volatile("ldmatrix.sync.aligned.m8n8.x4.shared.b16 {%0,%1,%2,%3}, [%4];"
                 : "=r"(r[0]), "=r"(r[1]), "=r"(r[2]), "=r"(r[3]) : "r"(addr));
}
__device__ __forceinline__ void mma16816(float* d, const uint32_t* a, const uint32_t* b) {
    asm volatile("mma.sync.aligned.m16n8k16.row.col.f32.bf16.bf16.f32 "
                 "{%0,%1,%2,%3}, {%4,%5,%6,%7}, {%8,%9}, {%0,%1,%2,%3};"
                 : "+f"(d[0]), "+f"(d[1]), "+f"(d[2]), "+f"(d[3])
                 : "r"(a[0]), "r"(a[1]), "r"(a[2]), "r"(a[3]), "r"(b[0]), "r"(b[1]));
}

#define SW128(o) ((o) ^ (((o) >> 3) & 0x70))

// ============ HMMA GEMM: C[M,N] = (Ahi+Alo)[M,K] @ (Bhi+Blo)[N,K]^T + bias ============
// 3-term double-bf16 emulation (hh + hl + lh). A row-major bf16 [M, lda];
// B row-major bf16 [N, ldb] (pre-transposed weights); C fp32 row-major [M, ldc].
// Block tile: 64(M) x 128(N) x 64(K), 8 warps (2x4), warp tile 32x32.
// SMEM/stage: Ah(8K) Al(8K) Bh(16K) Bl(16K) = 48KB; 2 stages = 96KB dynamic.
#define STAGE_B 49152
#define SM_AH 0
#define SM_AL 8192
#define SM_BH 16384
#define SM_BL 32768
#define HMMA_SMEM (2 * STAGE_B)

__global__ __launch_bounds__(256)
void hmma_gemm(const __nv_bfloat16* __restrict__ Ahi, const __nv_bfloat16* __restrict__ Alo, int lda,
               const __nv_bfloat16* __restrict__ Bhi, const __nv_bfloat16* __restrict__ Blo, int ldb,
               float* __restrict__ C, size_t ldc, int K, const float* __restrict__ bias)
{
    extern __shared__ char smem[];
    __shared__ float sbias[128];
    const int tid  = threadIdx.x;
    const int lane = tid & 31, wid = tid >> 5;
    const int wm = wid >> 2, wn = wid & 3;          // 2 x 4 warp grid
    const int m0 = blockIdx.y << 6;                  // 64-row tiles
    const int n0 = blockIdx.x << 7;                  // 128-col tiles
    const uint32_t sb = smem_u32(smem);

    if (tid < 128) sbias[tid] = bias[n0 + tid];

    const __nv_bfloat16* pAh = Ahi + (size_t)m0 * lda;
    const __nv_bfloat16* pAl = Alo + (size_t)m0 * lda;
    const __nv_bfloat16* pBh = Bhi + (size_t)n0 * ldb;
    const __nv_bfloat16* pBl = Blo + (size_t)n0 * ldb;

    // async stage loader: chunk c covers k in [c*64, c*64+64)
    auto load_stage = [&](int s, int c) {
        const int kb = c << 6;
        const uint32_t sa = sb + s * STAGE_B;
        // A hi/lo: 64 rows x 8 x 16B each
#pragma unroll
        for (int it = 0; it < 2; it++) {
            int idx = it * 256 + tid;
            int row = idx >> 3, cv = idx & 7;
            uint32_t so = SW128((uint32_t)(row * 128 + cv * 16));
            size_t g = (size_t)row * lda + kb + cv * 8;
            cp16(sa + SM_AH + so, pAh + g);
            cp16(sa + SM_AL + so, pAl + g);
        }
        // B hi/lo: 128 rows x 8 x 16B each
#pragma unroll
        for (int it = 0; it < 4; it++) {
            int idx = it * 256 + tid;
            int row = idx >> 3, cv = idx & 7;
            uint32_t so = SW128((uint32_t)(row * 128 + cv * 16));
            size_t g = (size_t)row * ldb + kb + cv * 8;
            cp16(sa + SM_BH + so, pBh + g);
            cp16(sa + SM_BL + so, pBl + g);
        }
        cp_commit();
    };

    float acc[2][4][4];
#pragma unroll
    for (int mi = 0; mi < 2; mi++)
#pragma unroll
        for (int ni = 0; ni < 4; ni++)
#pragma unroll
            for (int j = 0; j < 4; j++) acc[mi][ni][j] = 0.f;

    const int nch = K >> 6;
    load_stage(0, 0);

    for (int c = 0; c < nch; c++) {
        const int s = c & 1;
        if (c + 1 < nch) { load_stage(s ^ 1, c + 1); cp_wait<1>(); }
        else             { cp_wait<0>(); }
        __syncthreads();

        const uint32_t sa = sb + s * STAGE_B;
#pragma unroll
        for (int k16 = 0; k16 < 4; k16++) {
            uint32_t ah[2][4], al[2][4], bh[2][4], bl[2][4];
#pragma unroll
            for (int mi = 0; mi < 2; mi++) {
                uint32_t byte = (uint32_t)((wm * 32 + mi * 16 + (lane & 15)) * 128
                               + k16 * 32 + (lane >> 4) * 16);
                uint32_t so = SW128(byte);
                ldsm4(ah[mi], sa + SM_AH + so);
                ldsm4(al[mi], sa + SM_AL + so);
            }
#pragma unroll
            for (int pi = 0; pi < 2; pi++) {
                int row = wn * 32 + pi * 16 + ((lane >> 4) << 3) + (lane & 7);
                uint32_t byte = (uint32_t)(row * 128 + k16 * 32 + (((lane >> 3) & 1) << 4));
                uint32_t so = SW128(byte);
                ldsm4(bh[pi], sa + SM_BH + so);
                ldsm4(bl[pi], sa + SM_BL + so);
            }
#pragma unroll
            for (int mi = 0; mi < 2; mi++) {
#pragma unroll
                for (int ni = 0; ni < 4; ni++) {
                    const uint32_t* vbh = &bh[ni >> 1][(ni & 1) * 2];
                    const uint32_t* vbl = &bl[ni >> 1][(ni & 1) * 2];
                    mma16816(acc[mi][ni], ah[mi], vbh);   // hi*hi
                    mma16816(acc[mi][ni], ah[mi], vbl);   // hi*lo
                    mma16816(acc[mi][ni], al[mi], vbh);   // lo*hi
                }
            }
        }
        __syncthreads();
    }

    // epilogue: bias + store
#pragma unroll
    for (int mi = 0; mi < 2; mi++) {
        int r = m0 + wm * 32 + mi * 16 + (lane >> 2);
        float* c0 = C + (size_t)r * ldc + n0;
        float* c1 = c0 + 8 * ldc;
#pragma unroll
        for (int ni = 0; ni < 4; ni++) {
            int col = wn * 32 + ni * 8 + (lane & 3) * 2;
            float2 v0, v1;
            v0.x = acc[mi][ni][0] + sbias[col];
            v0.y = acc[mi][ni][1] + sbias[col + 1];
            v1.x = acc[mi][ni][2] + sbias[col];
            v1.y = acc[mi][ni][3] + sbias[col + 1];
            *(float2*)(c0 + col) = v0;
            *(float2*)(c1 + col) = v1;
        }
    }
}

// ---------------- fp32 SGEMM (prologue h0/c0 only) ----------------
template<int BM, int BN, int BK, int TM, int TN, int NT>
__global__ __launch_bounds__(NT)
void sgemm_kernel(const float* __restrict__ A, int lda,
                  const float* __restrict__ B, int ldb,
                  float* __restrict__ C, int ldc,
                  int K, const float* __restrict__ bias)
{
    __shared__ float As[BK][BM];
    __shared__ float Bs[BK][BN];
    const int tid = threadIdx.x;
    const size_t mbase = (size_t)blockIdx.y * BM;
    const size_t nbase = (size_t)blockIdx.x * BN;
    A += mbase * (size_t)lda;
    B += nbase;
    C += mbase * (size_t)ldc + nbase;
    if (bias) bias += nbase;
    const int tcol = (tid % (BN / TN)) * TN;
    const int trow = (tid / (BN / TN)) * TM;
    float acc[TM][TN];
#pragma unroll
    for (int i = 0; i < TM; i++)
#pragma unroll
        for (int j = 0; j < TN; j++) acc[i][j] = 0.f;
    constexpr int KV = BK / 4;
    for (int k0 = 0; k0 < K; k0 += BK) {
#pragma unroll
        for (int it = 0; it < (BM * KV) / NT; it++) {
            int idx = tid + it * NT;
            int row = idx / KV;
            int cv  = (idx % KV) * 4;
            float4 v = *(const float4*)(A + (size_t)row * lda + k0 + cv);
            As[cv + 0][row] = v.x; As[cv + 1][row] = v.y;
            As[cv + 2][row] = v.z; As[cv + 3][row] = v.w;
        }
#pragma unroll
        for (int it = 0; it < (BK * BN / 4) / NT; it++) {
            int idx = tid + it * NT;
            int row = idx / (BN / 4);
            int cv  = (idx % (BN / 4)) * 4;
            *(float4*)(&Bs[row][cv]) = *(const float4*)(B + (size_t)(k0 + row) * ldb + cv);
        }
        __syncthreads();
#pragma unroll
        for (int k = 0; k < BK; k++) {
            float ra[TM], rb[TN];
#pragma unroll
            for (int i = 0; i < TM; i += 4)
                *(float4*)(ra + i) = *(const float4*)(&As[k][trow + i]);
#pragma unroll
            for (int j = 0; j < TN; j += 4)
                *(float4*)(rb + j) = *(const float4*)(&Bs[k][tcol + j]);
#pragma unroll
            for (int i = 0; i < TM; i++)
#pragma unroll
                for (int j = 0; j < TN; j++)
                    acc[i][j] = fmaf(ra[i], rb[j], acc[i][j]);
        }
        __syncthreads();
    }
#pragma unroll
    for (int i = 0; i < TM; i++) {
#pragma unroll
        for (int j = 0; j < TN; j += 4) {
            float4 v;
            v.x = acc[i][j + 0]; v.y = acc[i][j + 1];
            v.z = acc[i][j + 2]; v.w = acc[i][j + 3];
            if (bias) {
                v.x += bias[tcol + j + 0]; v.y += bias[tcol + j + 1];
                v.z += bias[tcol + j + 2]; v.w += bias[tcol + j + 3];
            }
            *(float4*)(C + (size_t)(trow + i) * ldc + tcol + j) = v;
        }
    }
}

// ---------------- pointwise / conversion kernels ----------------
__global__ void mean_kernel(const float* __restrict__ X, float* __restrict__ mean)
{
    int idx = blockIdx.x * blockDim.x + threadIdx.x;
    int b = idx >> 11;
    int f = idx & (CF - 1);
    const float* xb = X + (size_t)b * CL * CF + f;
    float s = 0.f;
#pragma unroll 8
    for (int l = 0; l < CL; l++) s += xb[(size_t)l * CF];
    mean[idx] = s * (1.0f / CL);
}

__global__ void build_wcomb(const float* __restrict__ w_ih,
                            const float* __restrict__ w_hh,
                            float* __restrict__ wc)
{
    size_t idx = (size_t)blockIdx.x * blockDim.x + threadIdx.x;
    const size_t split = (size_t)(CE + CF) * G4;
    wc[idx] = (idx < split) ? w_ih[idx] : w_hh[idx - split];
}

__global__ void build_bcomb(const float* __restrict__ b_ih,
                            const float* __restrict__ b_hh,
                            float* __restrict__ bc)
{
    int i = blockIdx.x * blockDim.x + threadIdx.x;
    bc[i] = b_ih[i] + b_hh[i];
}

__device__ __forceinline__ void split1(float v, __nv_bfloat16& h, __nv_bfloat16& l) {
    h = __float2bfloat16(v);
    l = __float2bfloat16(v - __bfloat162float(h));
}

__global__ void split_kernel(const float* __restrict__ s,
                             __nv_bfloat16* __restrict__ hi, __nv_bfloat16* __restrict__ lo,
                             size_t n)
{
    size_t i = (size_t)blockIdx.x * blockDim.x + threadIdx.x;
    if (i >= n) return;
    split1(s[i], hi[i], lo[i]);
}

// split a column slice [ofs, ofs+cols) of the [CB, CEFH] lstm staging buffer
__global__ void split_rows(const float* __restrict__ s,
                           __nv_bfloat16* __restrict__ hi, __nv_bfloat16* __restrict__ lo,
                           int cols, int ofs)
{
    int i = blockIdx.x * blockDim.x + threadIdx.x;
    int b = i / cols, j = i - b * cols;
    size_t o = (size_t)b * CEFH + ofs + j;
    split1(s[o], hi[o], lo[o]);
}

// tiled transpose + split: out[n*K + k] = W[k*N + n]
__global__ void tconv(const float* __restrict__ W, int N, int K,
                      __nv_bfloat16* __restrict__ hi, __nv_bfloat16* __restrict__ lo)
{
    __shared__ float t[32][33];
    int n0 = blockIdx.x << 5, k0 = blockIdx.y << 5;
    int tx = threadIdx.x, ty = threadIdx.y;
#pragma unroll
    for (int i = ty; i < 32; i += 8)
        t[i][tx] = W[(size_t)(k0 + i) * N + n0 + tx];
    __syncthreads();
#pragma unroll
    for (int i = ty; i < 32; i += 8) {
        float v = t[tx][i];   // = W[k0+tx][n0+i]
        size_t o = (size_t)(n0 + i) * K + k0 + tx;
        split1(v, hi[o], lo[o]);
    }
}

__global__ void emb_gather(const int* __restrict__ y,
                           const float* __restrict__ emb,
                           float* __restrict__ lstm, int t)
{
    int idx = blockIdx.x * blockDim.x + threadIdx.x;
    int b = idx >> 9;
    int e = idx & (CE - 1);
    int tok = y[b * (CT + 1) + t];
    lstm[(size_t)b * CEFH + e] = emb[(size_t)tok * CE + e];
}

__global__ __launch_bounds__(256)
void attn_kernel(const float* __restrict__ X,
                 const float* __restrict__ xenc,
                 const float* __restrict__ xd,
                 const float* __restrict__ score_w,
                 const float* __restrict__ score_b,
                 float* __restrict__ alpha_out,
                 float* __restrict__ lstm, int t)
{
    const int b = blockIdx.x;
    __shared__ float sxd[CA];
    __shared__ float ssw[CA];
    __shared__ float ssc[CL];
    __shared__ float salpha[CL];
    const int tid = threadIdx.x;
    const int warp = tid >> 5, lane = tid & 31;

    for (int i = tid; i < CA; i += 256) {
        sxd[i] = xd[b * CA + i];
        ssw[i] = score_w[i];
    }
    __syncthreads();

    for (int l = warp; l < CL; l += 8) {
        const float* xe = xenc + ((size_t)b * CL + l) * CA;
        float acc = 0.f;
        for (int a = lane; a < CA; a += 32)
            acc += tanhf(xe[a] + sxd[a]) * ssw[a];
#pragma unroll
        for (int off = 16; off; off >>= 1)
            acc += __shfl_xor_sync(0xffffffffu, acc, off);
        if (lane == 0) ssc[l] = acc + score_b[0];
    }
    __syncthreads();

    if (warp == 0) {
        float v0 = ssc[lane], v1 = ssc[lane + 32];
        float m = fmaxf(v0, v1);
#pragma unroll
        for (int off = 16; off; off >>= 1)
            m = fmaxf(m, __shfl_xor_sync(0xffffffffu, m, off));
        float e0 = expf(v0 - m), e1 = expf(v1 - m);
        float s = e0 + e1;
#pragma unroll
        for (int off = 16; off; off >>= 1)
            s += __shfl_xor_sync(0xffffffffu, s, off);
        float inv = 1.0f / s;
        salpha[lane]      = e0 * inv;
        salpha[lane + 32] = e1 * inv;
    }
    __syncthreads();

    if (alpha_out && tid < CL)
        alpha_out[((size_t)b * CT + t) * CL + tid] = salpha[tid];

    const float* Xb = X + (size_t)b * CL * CF;
    for (int f = tid; f < CF; f += 256) {
        float acc = 0.f;
#pragma unroll 8
        for (int l = 0; l < CL; l++)
            acc += salpha[l] * Xb[(size_t)l * CF + f];
        lstm[(size_t)b * CEFH + CE + f] = acc;
    }
}

__device__ __forceinline__ float sigm(float x) { return 1.0f / (1.0f + expf(-x)); }

// LSTM pointwise: update c; write h2 as hi/lo split into the lstm hi/lo h-slot
__global__ void lstm_cell(const float* __restrict__ gates,
                          float* __restrict__ c,
                          __nv_bfloat16* __restrict__ lhi,
                          __nv_bfloat16* __restrict__ llo)
{
    int idx = blockIdx.x * blockDim.x + threadIdx.x;
    int b = idx >> 10;
    int j = idx & (CH - 1);
    const float* g = gates + (size_t)b * G4;
    float gi = sigm(g[j]);
    float gf = sigm(g[j + CH]);
    float gg = tanhf(g[j + 2 * CH]);
    float go = sigm(g[j + 3 * CH]);
    float c2 = gf * c[idx] + gi * gg;
    c[idx] = c2;
    float h2 = go * tanhf(c2);
    size_t o = (size_t)b * CEFH + CE + CF + j;
    split1(h2, lhi[o], llo[o]);
}

// ---------------- host-side launch helpers ----------------
static void gemm64(const float* A, int lda, const float* B, int ldb,
                   float* C, int ldc, int M, int N, int K, const float* bias)
{
    dim3 grid(N / 64, M / 64);
    sgemm_kernel<64, 64, 8, 8, 4, 128><<<grid, 128>>>(A, lda, B, ldb, C, ldc, K, bias);
}
static void tmma(const __nv_bfloat16* Ah, const __nv_bfloat16* Al, int lda,
                 const __nv_bfloat16* Bh, const __nv_bfloat16* Bl, int ldb,
                 float* C, size_t ldc, int M, int N, int K, const float* bias)
{
    dim3 grid(N / 128, M / 64);
    hmma_gemm<<<grid, 256, HMMA_SMEM>>>(Ah, Al, lda, Bh, Bl, ldb, C, ldc, K, bias);
}

extern "C" void kernel_launch(void* const* d_in, const int* in_sizes, int n_in,
                              void* d_out, int out_size)
{
    const float* X       = (const float*)d_in[0];
    const int*   y       = (const int*)  d_in[1];
    const float* emb     = (const float*)d_in[2];
    const float* fc1_w   = (const float*)d_in[3];
    const float* fc1_b   = (const float*)d_in[4];
    const float* fc2_w   = (const float*)d_in[5];
    const float* fc2_b   = (const float*)d_in[6];
    const float* score_w = (const float*)d_in[7];
    const float* score_b = (const float*)d_in[8];
    const float* sm_w    = (const float*)d_in[9];
    const float* sm_b    = (const float*)d_in[10];
    const float* lm_w    = (const float*)d_in[11];
    const float* lm_b    = (const float*)d_in[12];
    const float* w_ih    = (const float*)d_in[13];
    const float* b_ih    = (const float*)d_in[14];
    const float* w_hh    = (const float*)d_in[15];
    const float* b_hh    = (const float*)d_in[16];
    const float* out_w   = (const float*)d_in[17];
    const float* out_b   = (const float*)d_in[18];

    float* out_logits = (float*)d_out;
    const size_t logits_elems = (size_t)CB * CT * CV;
    const size_t total_elems  = logits_elems + (size_t)CB * CT * CL;
    float* out_alpha = ((size_t)out_size >= total_elems) ? (out_logits + logits_elems) : nullptr;

    float *mean, *c, *xenc, *xd, *lstm, *gates, *wc, *bc;
    cudaGetSymbolAddress((void**)&mean,  g_mean);
    cudaGetSymbolAddress((void**)&c,     g_c);
    cudaGetSymbolAddress((void**)&xenc,  g_xenc);
    cudaGetSymbolAddress((void**)&xd,    g_xd);
    cudaGetSymbolAddress((void**)&lstm,  g_lstm);
    cudaGetSymbolAddress((void**)&gates, g_gates);
    cudaGetSymbolAddress((void**)&wc,    g_wc);
    cudaGetSymbolAddress((void**)&bc,    g_bc);
    __nv_bfloat16 *lhi, *llo, *Xhi, *Xlo, *owh, *owl, *wch, *wcl, *f2h, *f2l, *f1h, *f1l;
    cudaGetSymbolAddress((void**)&lhi, g_lstm_hi);  cudaGetSymbolAddress((void**)&llo, g_lstm_lo);
    cudaGetSymbolAddress((void**)&Xhi, g_X_hi);     cudaGetSymbolAddress((void**)&Xlo, g_X_lo);
    cudaGetSymbolAddress((void**)&owh, g_owT_hi);   cudaGetSymbolAddress((void**)&owl, g_owT_lo);
    cudaGetSymbolAddress((void**)&wch, g_wcT_hi);   cudaGetSymbolAddress((void**)&wcl, g_wcT_lo);
    cudaGetSymbolAddress((void**)&f2h, g_f2T_hi);   cudaGetSymbolAddress((void**)&f2l, g_f2T_lo);
    cudaGetSymbolAddress((void**)&f1h, g_f1T_hi);   cudaGetSymbolAddress((void**)&f1l, g_f1T_lo);

    cudaFuncSetAttribute(hmma_gemm, cudaFuncAttributeMaxDynamicSharedMemorySize, HMMA_SMEM);

    dim3 tb(32, 8);

    // ---- prologue ----
    mean_kernel<<<(CB * CF) / 256, 256>>>(X, mean);
    gemm64(mean, CF, sm_w, CH, lstm + (CE + CF), CEFH, CB, CH, CF, sm_b);   // h0 (fp32 staging)
    gemm64(mean, CF, lm_w, CH, c, CH, CB, CH, CF, lm_b);                    // c0
    build_wcomb<<<(unsigned)(((size_t)CEFH * G4) / 256), 256>>>(w_ih, w_hh, wc);
    build_bcomb<<<G4 / 256, 256>>>(b_ih, b_hh, bc);
    // transpose + bf16-split weights: out[n][k] = W[k][n]
    tconv<<<dim3(CV / 32, CH / 32),   tb>>>(out_w, CV, CH,   owh, owl);
    tconv<<<dim3(G4 / 32, CEFH / 32), tb>>>(wc,    G4, CEFH, wch, wcl);
    tconv<<<dim3(CA / 32, CF / 32),   tb>>>(fc2_w, CA, CF,   f2h, f2l);
    tconv<<<dim3(CA / 32, CH / 32),   tb>>>(fc1_w, CA, CH,   f1h, f1l);
    // split X and h0
    {
        size_t n = (size_t)CB * CL * CF;
        split_kernel<<<(unsigned)((n + 255) / 256), 256>>>(X, Xhi, Xlo, n);
    }
    split_rows<<<(CB * CH) / 256, 256>>>(lstm, lhi, llo, CH, CE + CF);
    // x_enc = X @ fc2_w + fc2_b  (tensor)
    tmma(Xhi, Xlo, CF, f2h, f2l, CF, xenc, CA, CB * CL, CA, CF, fc2_b);

    // ---- decode loop ----
    for (int t = 0; t < CT; t++) {
        // xd = h @ fc1_w + fc1_b
        tmma(lhi + (CE + CF), llo + (CE + CF), CEFH, f1h, f1l, CH, xd, CA, CB, CA, CH, fc1_b);
        emb_gather<<<(CB * CE) / 256, 256>>>(y, emb, lstm, t);
        attn_kernel<<<CB, 256>>>(X, xenc, xd, score_w, score_b, out_alpha, lstm, t);
        // split emb|context into hi/lo (h slot maintained by lstm_cell)
        split_rows<<<(CB * (CE + CF)) / 256, 256>>>(lstm, lhi, llo, CE + CF, 0);
        // gates = lstm_in @ [w_ih; w_hh] + (b_ih + b_hh)
        tmma(lhi, llo, CEFH, wch, wcl, CEFH, gates, G4, CB, G4, CEFH, bc);
        // LSTM pointwise -> c, h2 (hi/lo)
        lstm_cell<<<(CB * CH) / 256, 256>>>(gates, c, lhi, llo);
        // logits = h2 @ out_w + out_b
        tmma(lhi + (CE + CF), llo + (CE + CF), CEFH, owh, owl, CH,
             out_logits + (size_t)t * CV, (size_t)CT * CV, CB, CV, CH, out_b);
    }
}